// round 17
// baseline (speedup 1.0000x reference)
#include <cuda_runtime.h>
#include <cuda.h>
#include <math.h>

#define BB 4
#define NN 65536
#define KK 16
#define HH 64
#define TPB 128
#define NPTS (BB * NN)

// ---- TMA-kernel smem layout (dynamic) ----
// One 128B-aligned slot per gather4 (HW requirement for tile::gather4 dst).
// Slot (tid, g) at (tid*4+g)*128; rows of the gather land at +0/16/32/48.
#define SM_NBR_BYTES (TPB * 4 * 128)        // 65536
#define SM_FEAT_OFF SM_NBR_BYTES
#define SM_FEAT_BYTES (TPB * 10 * 4)        // 5120
#define SM_MBAR_OFF (SM_FEAT_OFF + SM_FEAT_BYTES)
#define SM_TOTAL (SM_MBAR_OFF + 16)         // 70672

// Scratch: xyz repacked as float4 per point (w unused). 4 MB.
__device__ float4 g_xyz4[NPTS];
__device__ int g_idx_is64;

// ---- helpers ----
__device__ __forceinline__ uint32_t smem_u32(const void* p) {
    uint32_t a;
    asm("{ .reg .u64 t; cvta.to.shared.u64 t, %1; cvt.u32.u64 %0, t; }" : "=r"(a) : "l"(p));
    return a;
}
__device__ __forceinline__ unsigned long long pk2(float lo, float hi) {
    unsigned long long d;
    asm("mov.b64 %0, {%1, %2};" : "=l"(d) : "f"(lo), "f"(hi));
    return d;
}
__device__ __forceinline__ unsigned long long ffma2(
    unsigned long long a, unsigned long long b, unsigned long long c) {
    unsigned long long d;
    asm("fma.rn.f32x2 %0, %1, %2, %3;" : "=l"(d) : "l"(a), "l"(b), "l"(c));
    return d;
}
__device__ __forceinline__ void upk2(unsigned long long v, float& lo, float& hi) {
    asm("mov.b64 {%0, %1}, %2;" : "=f"(lo), "=f"(hi) : "l"(v));
}
__device__ __forceinline__ void mbar_init(uint32_t a, uint32_t cnt) {
    asm volatile("mbarrier.init.shared.b64 [%0], %1;" :: "r"(a), "r"(cnt) : "memory");
}
__device__ __forceinline__ void mbar_expect_tx(uint32_t a, uint32_t bytes) {
    asm volatile("mbarrier.arrive.expect_tx.shared.b64 _, [%0], %1;" :: "r"(a), "r"(bytes) : "memory");
}
__device__ __forceinline__ void mbar_wait(uint32_t a, uint32_t parity) {
    asm volatile(
        "{\n\t.reg .pred P;\n\t"
        "L1_%=:\n\t"
        "mbarrier.try_wait.parity.acquire.cta.shared::cta.b64 P, [%0], %1, 0x989680;\n\t"
        "@P bra.uni L2_%=;\n\t"
        "bra.uni L1_%=;\n\t"
        "L2_%=:\n\t}"
        :: "r"(a), "r"(parity) : "memory");
}
// TMA sparse row gather: fetch 4 rows (16B each) of the [4 x NPTS] fp32 tensor
// into one 128B-aligned smem slot.
__device__ __forceinline__ void tma_gather4(
    uint32_t dst, const void* tmap, int r0, int r1, int r2, int r3, uint32_t mbar) {
    asm volatile(
        "cp.async.bulk.tensor.2d.shared::cta.global.tile::gather4.mbarrier::complete_tx::bytes "
        "[%0], [%1, {%2, %3, %4, %5, %6}], [%7];"
        :: "r"(dst), "l"(tmap), "r"(0), "r"(r0), "r"(r1), "r"(r2), "r"(r3), "r"(mbar)
        : "memory");
}

// ---------------------------------------------------------------------------
// Transpose pos (B,3,N) -> g_xyz4 (float4). Warp 0 of block 0 detects idx dtype
// (int64 values < 65536 have all-zero odd words; int32 words are random).
// ---------------------------------------------------------------------------
__global__ void transpose_pos_kernel(const float* __restrict__ pos,
                                     const unsigned* __restrict__ idxw) {
    if (blockIdx.x == 0 && threadIdx.x < 32) {
        unsigned v = idxw[4 * threadIdx.x + 1] | idxw[4 * threadIdx.x + 3];
        unsigned any = __ballot_sync(0xffffffffu, v != 0u);
        if (threadIdx.x == 0) g_idx_is64 = (any == 0u) ? 1 : 0;
    }
    int t = blockIdx.x * blockDim.x + threadIdx.x;
    if (t >= NPTS) return;
    int b = t >> 16;
    int n = t & (NN - 1);
    const float* p = pos + (size_t)b * 3 * NN;
    float4 v;
    v.x = p[n];
    v.y = p[NN + n];
    v.z = p[2 * NN + n];
    v.w = 0.0f;
    g_xyz4[t] = v;
}

// dtype-adaptive index load (16 ints, masked to [0, NN))
__device__ __forceinline__ void load_ids(const void* idxv, int t, int* id) {
    if (g_idx_is64 != 0) {
        const int4* q = (const int4*)((const char*)idxv + (size_t)t * (KK * 8));
#pragma unroll
        for (int i = 0; i < 8; i++) {
            int4 v = q[i];
            id[2 * i + 0] = v.x & (NN - 1);
            id[2 * i + 1] = v.z & (NN - 1);
        }
    } else {
        const int4* q = (const int4*)((const char*)idxv + (size_t)t * (KK * 4));
#pragma unroll
        for (int i = 0; i < 4; i++) {
            int4 v = q[i];
            id[4 * i + 0] = v.x & (NN - 1);
            id[4 * i + 1] = v.y & (NN - 1);
            id[4 * i + 2] = v.z & (NN - 1);
            id[4 * i + 3] = v.w & (NN - 1);
        }
    }
}

__device__ __forceinline__ float dist_max(const float* dist, int t) {
    const float4* d4 = (const float4*)(dist + (size_t)t * KK);
    float4 da = d4[0], db = d4[1], dc = d4[2], dd = d4[3];
    float m0 = fmaxf(fmaxf(da.x, da.y), fmaxf(da.z, da.w));
    float m1 = fmaxf(fmaxf(db.x, db.y), fmaxf(db.z, db.w));
    float m2 = fmaxf(fmaxf(dc.x, dc.y), fmaxf(dc.z, dc.w));
    float m3 = fmaxf(fmaxf(dd.x, dd.y), fmaxf(dd.z, dd.w));
    return fmaxf(fmaxf(m0, m1), fmaxf(m2, m3));
}

// Phase 2 (shared): matvec + relu; 16 consecutive lanes cover one point's 64
// channels -> warp stores 512B contiguous (4 L1 wavefronts).
__device__ __forceinline__ void phase2_run(
    const float (*fs)[10], long blk_base, int c, int sub,
    const unsigned long long* Wxy, const unsigned long long* Wzw,
    unsigned long long Bxy, unsigned long long Bzw, float* out)
{
#pragma unroll
    for (int it = 0; it < 16; it++) {
        int pl = it * 8 + sub;
        unsigned long long axy = Bxy, azw = Bzw;
#pragma unroll
        for (int j = 0; j < 10; j++) {
            float f = fs[pl][j];
            unsigned long long ff = pk2(f, f);
            axy = ffma2(ff, Wxy[j], axy);
            azw = ffma2(ff, Wzw[j], azw);
        }
        float4 acc;
        upk2(axy, acc.x, acc.y);
        upk2(azw, acc.z, acc.w);
        acc.x = fmaxf(acc.x, 0.0f);
        acc.y = fmaxf(acc.y, 0.0f);
        acc.z = fmaxf(acc.z, 0.0f);
        acc.w = fmaxf(acc.w, 0.0f);
        ((float4*)(out + (blk_base + pl) * HH))[c] = acc;
    }
}

// ---------------------------------------------------------------------------
// TMA-gather main kernel: neighbor fetch runs on the TMA engine (L2 -> SMEM),
// bypassing the L1tex wavefront-replay floor that bounds the LDG version.
// ---------------------------------------------------------------------------
__global__ __launch_bounds__(TPB) void point_embed_tma_kernel(
    const __grid_constant__ CUtensorMap tmap,
    const void* __restrict__ idxv,
    const float* __restrict__ dist,
    const float* __restrict__ W,
    const float* __restrict__ bias,
    float* __restrict__ out)
{
    extern __shared__ __align__(128) unsigned char smem[];
    float (*feat_s)[10] = (float (*)[10])(smem + SM_FEAT_OFF);
    uint32_t nbr_u32 = smem_u32(smem);
    uint32_t mbar_u32 = smem_u32(smem + SM_MBAR_OFF);

    int tid = threadIdx.x;
    int t = blockIdx.x * TPB + tid;
    int base = (t >> 16) << 16;

    if (tid == 0) {
        mbar_init(mbar_u32, 1);
        // fence so TMA (async proxy) observes the initialized barrier
        asm volatile("fence.proxy.async.shared::cta;" ::: "memory");
        mbar_expect_tx(mbar_u32, TPB * KK * 16);   // 32768 B total
    }
    __syncthreads();

    // ---- issue 4 gather4 per thread (16 neighbors), 128B-aligned slots ----
    int id[KK];
    load_ids(idxv, t, id);
    uint32_t dst = nbr_u32 + tid * (4 * 128);
#pragma unroll
    for (int g = 0; g < 4; g++)
        tma_gather4(dst + g * 128, &tmap,
                    base + id[4 * g + 0], base + id[4 * g + 1],
                    base + id[4 * g + 2], base + id[4 * g + 3], mbar_u32);

    // ---- overlap with TMA: center point, dist max, W hoist ----
    float4 p = g_xyz4[t];
    float md = dist_max(dist, t);

    int c = tid & 15;
    int sub = tid >> 4;
    unsigned long long Wxy[10], Wzw[10];
#pragma unroll
    for (int j = 0; j < 10; j++) {
        float4 w = ((const float4*)W)[j * 16 + c];
        Wxy[j] = pk2(w.x, w.y);
        Wzw[j] = pk2(w.z, w.w);
    }
    float4 bb = ((const float4*)bias)[c];
    unsigned long long Bxy = pk2(bb.x, bb.y);
    unsigned long long Bzw = pk2(bb.z, bb.w);

    // ---- wait, consume neighbors (lane-rotated k: 4 disjoint bank quads) ----
    mbar_wait(mbar_u32, 0);

    float mnx = -INFINITY, mny = -INFINITY, mnz = -INFINITY;
    float mdx = -INFINITY, mdy = -INFINITY, mdz = -INFINITY;
    int lane = tid & 31;
    const unsigned char* my = smem + tid * (4 * 128);
#pragma unroll
    for (int i = 0; i < KK; i++) {
        int k = (i + lane) & 15;           // rotate -> (k&3) differs across lanes
        float4 q = *(const float4*)(my + (k >> 2) * 128 + (k & 3) * 16);
        mnx = fmaxf(mnx, q.x);
        mny = fmaxf(mny, q.y);
        mnz = fmaxf(mnz, q.z);
        mdx = fmaxf(mdx, p.x - q.x);
        mdy = fmaxf(mdy, p.y - q.y);
        mdz = fmaxf(mdz, p.z - q.z);
    }

    feat_s[tid][0] = p.x;  feat_s[tid][1] = p.y;  feat_s[tid][2] = p.z;
    feat_s[tid][3] = mnx;  feat_s[tid][4] = mny;  feat_s[tid][5] = mnz;
    feat_s[tid][6] = mdx;  feat_s[tid][7] = mdy;  feat_s[tid][8] = mdz;
    feat_s[tid][9] = md;

    __syncthreads();
    phase2_run(feat_s, (long)blockIdx.x * TPB, c, sub, Wxy, Wzw, Bxy, Bzw, out);
}

// ---------------------------------------------------------------------------
// Fallback (R14, best LDG-based kernel) — used if tensormap setup fails.
// ---------------------------------------------------------------------------
__global__ __launch_bounds__(TPB, 4) void point_embed_kernel(
    const void* __restrict__ idxv,
    const float* __restrict__ dist,
    const float* __restrict__ W,
    const float* __restrict__ bias,
    float* __restrict__ out)
{
    __shared__ float feat_s[TPB][10];
    int tid = threadIdx.x;
    int t = blockIdx.x * TPB + tid;
    int base = (t >> 16) << 16;

    int id[KK];
    load_ids(idxv, t, id);

    float4 p = g_xyz4[t];
    float mnx = -INFINITY, mny = -INFINITY, mnz = -INFINITY;
    float mdx = -INFINITY, mdy = -INFINITY, mdz = -INFINITY;
#pragma unroll
    for (int k = 0; k < KK; k++) {
        float4 q = g_xyz4[base + id[k]];
        mnx = fmaxf(mnx, q.x);
        mny = fmaxf(mny, q.y);
        mnz = fmaxf(mnz, q.z);
        mdx = fmaxf(mdx, p.x - q.x);
        mdy = fmaxf(mdy, p.y - q.y);
        mdz = fmaxf(mdz, p.z - q.z);
    }
    float md = dist_max(dist, t);

    feat_s[tid][0] = p.x;  feat_s[tid][1] = p.y;  feat_s[tid][2] = p.z;
    feat_s[tid][3] = mnx;  feat_s[tid][4] = mny;  feat_s[tid][5] = mnz;
    feat_s[tid][6] = mdx;  feat_s[tid][7] = mdy;  feat_s[tid][8] = mdz;
    feat_s[tid][9] = md;

    int c = tid & 15;
    unsigned long long Wxy[10], Wzw[10];
#pragma unroll
    for (int j = 0; j < 10; j++) {
        float4 w = ((const float4*)W)[j * 16 + c];
        Wxy[j] = pk2(w.x, w.y);
        Wzw[j] = pk2(w.z, w.w);
    }
    float4 bb = ((const float4*)bias)[c];
    unsigned long long Bxy = pk2(bb.x, bb.y);
    unsigned long long Bzw = pk2(bb.z, bb.w);

    __syncthreads();
    phase2_run(feat_s, (long)blockIdx.x * TPB, c, tid >> 4, Wxy, Wzw, Bxy, Bzw, out);
}

// ---------------------------------------------------------------------------
typedef CUresult (CUDAAPI *PFN_encTiled)(
    CUtensorMap*, CUtensorMapDataType, cuuint32_t, void*,
    const cuuint64_t*, const cuuint64_t*, const cuuint32_t*, const cuuint32_t*,
    CUtensorMapInterleave, CUtensorMapSwizzle, CUtensorMapL2promotion,
    CUtensorMapFloatOOBfill);

extern "C" void kernel_launch(void* const* d_in, const int* in_sizes, int n_in,
                              void* d_out, int out_size) {
    const float* pos  = (const float*)d_in[0];
    const void*  idx  = d_in[1];
    const float* dist = (const float*)d_in[2];
    const float* W    = (const float*)d_in[3];
    const float* bias = (const float*)d_in[4];
    float* out = (float*)d_out;

    transpose_pos_kernel<<<(NPTS + 255) / 256, 256>>>(pos, (const unsigned*)idx);

    // Build gather4 tensormap: [4 floats x NPTS rows] over g_xyz4, row = point.
    bool use_tma = false;
    CUtensorMap tmap;
    void* fn = nullptr;
    cudaDriverEntryPointQueryResult qr = cudaDriverEntryPointSymbolNotFound;
    if (cudaGetDriverEntryPointByVersion("cuTensorMapEncodeTiled", &fn, 12000,
                                         cudaEnableDefault, &qr) == cudaSuccess &&
        qr == cudaDriverEntryPointSuccess && fn != nullptr) {
        void* xyz_ptr = nullptr;
        if (cudaGetSymbolAddress(&xyz_ptr, g_xyz4) == cudaSuccess && xyz_ptr) {
            cuuint64_t dims[2]    = {4, (cuuint64_t)NPTS};
            cuuint64_t gstride[1] = {16};
            cuuint32_t box[2]     = {4, 1};
            cuuint32_t estr[2]    = {1, 1};
            PFN_encTiled enc = (PFN_encTiled)fn;
            if (enc(&tmap, CU_TENSOR_MAP_DATA_TYPE_FLOAT32, 2, xyz_ptr,
                    dims, gstride, box, estr,
                    CU_TENSOR_MAP_INTERLEAVE_NONE, CU_TENSOR_MAP_SWIZZLE_NONE,
                    CU_TENSOR_MAP_L2_PROMOTION_NONE,
                    CU_TENSOR_MAP_FLOAT_OOB_FILL_NONE) == CUDA_SUCCESS)
                use_tma = true;
        }
    }

    if (use_tma) {
        cudaFuncSetAttribute(point_embed_tma_kernel,
                             cudaFuncAttributeMaxDynamicSharedMemorySize, SM_TOTAL);
        point_embed_tma_kernel<<<NPTS / TPB, TPB, SM_TOTAL>>>(
            tmap, idx, dist, W, bias, out);
    } else {
        point_embed_kernel<<<NPTS / TPB, TPB>>>(idx, dist, W, bias, out);
    }
}